// round 3
// baseline (speedup 1.0000x reference)
#include <cuda_runtime.h>
#include <math.h>

#define B 4
#define T 4096
#define S 4096
#define E 512
#define H 64

// scale = H^-0.5 = 0.125, folded into the q table.
#define SCALE 0.125f

// Scratch (device globals: allocation-free per harness rules)
__device__ float g_q[B * T * H];     // 4 MB : SCALE * tanh(x*qw + qb)
__device__ float g_k[B * S * H];     // 4 MB : tanh(emb @ kw^T + kb)
__device__ float g_v[B * S * H];     // 4 MB : tanh(emb @ vw^T), later v/denom in place
__device__ float g_denom[B * S];     // 64 KB

// ---------------------------------------------------------------------------
// Kernel A: q table. g_q[(b*T+t)*H+h] = SCALE * tanh(x[b,t]*qw[h] + qb[h])
// ---------------------------------------------------------------------------
__global__ __launch_bounds__(256) void q_kernel(const float* __restrict__ x,
                                                const float* __restrict__ qw,
                                                const float* __restrict__ qb) {
    int idx = blockIdx.x * 256 + threadIdx.x;   // over B*T*H
    int h  = idx & (H - 1);
    int bt = idx >> 6;
    g_q[idx] = SCALE * tanhf(x[bt] * qw[h] + qb[h]);
}

// ---------------------------------------------------------------------------
// Kernel B: k and v. Block = 64 rows (b,s) x 64 h; loop E in chunks of 32.
// 256 threads as 16x16, each owns a 4(row) x 4(h) micro-tile for both k and v.
// ---------------------------------------------------------------------------
__global__ __launch_bounds__(256) void kv_kernel(const float* __restrict__ emb,
                                                 const float* __restrict__ kw,
                                                 const float* __restrict__ kb,
                                                 const float* __restrict__ vw) {
    __shared__ __align__(16) float embT[32][68];   // [e][row]
    __shared__ __align__(16) float kwT[32][68];    // [e][h]
    __shared__ __align__(16) float vwT[32][68];    // [e][h]

    const int r0  = blockIdx.x * 64;               // global (b*S+s) row base
    const int tid = threadIdx.x;
    const int ty  = tid >> 4;                      // 0..15 -> row group
    const int tx  = tid & 15;                      // 0..15 -> h group

    float ak[4][4] = {};
    float av[4][4] = {};

    for (int e0 = 0; e0 < E; e0 += 32) {
        __syncthreads();
        for (int j = tid; j < 64 * 32; j += 256) {
            int r = j >> 5, e = j & 31;
            embT[e][r] = emb[(size_t)(r0 + r) * E + e0 + e];
            kwT[e][r]  = kw[(size_t)r * E + e0 + e];
            vwT[e][r]  = vw[(size_t)r * E + e0 + e];
        }
        __syncthreads();
#pragma unroll 8
        for (int e = 0; e < 32; e++) {
            float4 a  = *(const float4*)&embT[e][4 * ty];
            float4 k4 = *(const float4*)&kwT[e][4 * tx];
            float4 v4 = *(const float4*)&vwT[e][4 * tx];
            float ar[4] = {a.x, a.y, a.z, a.w};
            float kr[4] = {k4.x, k4.y, k4.z, k4.w};
            float vr[4] = {v4.x, v4.y, v4.z, v4.w};
#pragma unroll
            for (int i = 0; i < 4; i++)
#pragma unroll
                for (int j = 0; j < 4; j++) {
                    ak[i][j] += ar[i] * kr[j];
                    av[i][j] += ar[i] * vr[j];
                }
        }
    }

#pragma unroll
    for (int i = 0; i < 4; i++) {
        int row = r0 + 4 * ty + i;
#pragma unroll
        for (int j = 0; j < 4; j++) {
            int h = 4 * tx + j;
            g_k[(size_t)row * H + h] = tanhf(ak[i][j] + kb[h]);
            g_v[(size_t)row * H + h] = tanhf(av[i][j]);
        }
    }
}

// ---------------------------------------------------------------------------
// Kernel C: denom[b,s] = sum_t exp(L[t,s]).  Block = 64 s cols, loop all T.
// ---------------------------------------------------------------------------
__global__ __launch_bounds__(256) void denom_kernel() {
    __shared__ __align__(16) float kT[64][68];  // [h][s]
    __shared__ __align__(16) float qT[64][68];  // [h][t]
    __shared__ float dsh[64];

    const int b   = blockIdx.y;
    const int s0  = blockIdx.x * 64;
    const int tid = threadIdx.x;
    const int ty  = tid >> 4;   // t group
    const int tx  = tid & 15;   // s group

    for (int j = tid; j < 4096; j += 256) {
        int r = j >> 6, h = j & 63;
        kT[h][r] = g_k[(size_t)(b * S + s0 + r) * H + h];
    }
    if (tid < 64) dsh[tid] = 0.0f;

    float dsum[4] = {0.f, 0.f, 0.f, 0.f};

    for (int t0 = 0; t0 < T; t0 += 64) {
        __syncthreads();
        for (int j = tid; j < 4096; j += 256) {
            int r = j >> 6, h = j & 63;
            qT[h][r] = g_q[(size_t)(b * T + t0 + r) * H + h];
        }
        __syncthreads();

        float L[4][4] = {};
#pragma unroll 8
        for (int h = 0; h < 64; h++) {
            float4 qa = *(const float4*)&qT[h][4 * ty];
            float4 ka = *(const float4*)&kT[h][4 * tx];
            float qr[4] = {qa.x, qa.y, qa.z, qa.w};
            float kr[4] = {ka.x, ka.y, ka.z, ka.w};
#pragma unroll
            for (int i = 0; i < 4; i++)
#pragma unroll
                for (int j = 0; j < 4; j++) L[i][j] += qr[i] * kr[j];
        }
#pragma unroll
        for (int i = 0; i < 4; i++)
#pragma unroll
            for (int j = 0; j < 4; j++) dsum[j] += __expf(L[i][j]);
    }

    __syncthreads();
#pragma unroll
    for (int j = 0; j < 4; j++) atomicAdd(&dsh[4 * tx + j], dsum[j]);
    __syncthreads();
    if (tid < 64) g_denom[b * S + s0 + tid] = dsh[tid];
}

// ---------------------------------------------------------------------------
// Kernel D: v' = v / denom (in place)
// ---------------------------------------------------------------------------
__global__ __launch_bounds__(256) void scale_v_kernel() {
    int idx = blockIdx.x * 256 + threadIdx.x;  // over B*S*H
    g_v[idx] = g_v[idx] / g_denom[idx >> 6];
}

// ---------------------------------------------------------------------------
// Kernel E: out[b,t] = pb + sum_h pw[h]*tanh( sum_s exp(L[t,s]) * v'[s,h] )
// Block = 64 t rows x all 64 h; loop s in chunks of 64.
// Stage 1: L tile -> exp -> Wt smem (transposed). Stage 2: out += Wt^T @ v'.
// ---------------------------------------------------------------------------
#define SMEM_E ((4 * 64 * 68 + 64 * 17) * 4)

__global__ __launch_bounds__(256) void out_kernel(const float* __restrict__ pw,
                                                  const float* __restrict__ pb,
                                                  float* __restrict__ out) {
    extern __shared__ __align__(16) float sm[];
    float(*qT)[68]  = (float(*)[68])sm;                  // [h][t]
    float(*kT)[68]  = (float(*)[68])(sm + 1 * 64 * 68);  // [h][s]
    float(*Wt)[68]  = (float(*)[68])(sm + 2 * 64 * 68);  // [s][t]
    float(*vs)[68]  = (float(*)[68])(sm + 3 * 64 * 68);  // [s][h]
    float(*red)[17] = (float(*)[17])(sm + 4 * 64 * 68);  // [t][tx]

    const int b   = blockIdx.y;
    const int t0  = blockIdx.x * 64;
    const int tid = threadIdx.x;
    const int ty  = tid >> 4;   // t group (stage1), t group (stage2)
    const int tx  = tid & 15;   // s group (stage1), h group (stage2)

    for (int j = tid; j < 4096; j += 256) {
        int t = j >> 6, h = j & 63;
        qT[h][t] = g_q[(size_t)(b * T + t0 + t) * H + h];
    }

    float ao[4][4] = {};

    for (int s0 = 0; s0 < S; s0 += 64) {
        __syncthreads();
        for (int j = tid; j < 4096; j += 256) {
            int s = j >> 6, h = j & 63;
            float kv = g_k[(size_t)(b * S + s0 + s) * H + h];
            float vv = g_v[(size_t)(b * S + s0 + s) * H + h];
            kT[h][s] = kv;
            vs[s][h] = vv;
        }
        __syncthreads();

        // Stage 1: L[t,s] tile, exp, store transposed
        float L[4][4] = {};
#pragma unroll 8
        for (int h = 0; h < 64; h++) {
            float4 qa = *(const float4*)&qT[h][4 * ty];
            float4 ka = *(const float4*)&kT[h][4 * tx];
            float qr[4] = {qa.x, qa.y, qa.z, qa.w};
            float kr[4] = {ka.x, ka.y, ka.z, ka.w};
#pragma unroll
            for (int i = 0; i < 4; i++)
#pragma unroll
                for (int j = 0; j < 4; j++) L[i][j] += qr[i] * kr[j];
        }
#pragma unroll
        for (int i = 0; i < 4; i++)
#pragma unroll
            for (int j = 0; j < 4; j++) Wt[4 * tx + j][4 * ty + i] = __expf(L[i][j]);
        __syncthreads();

        // Stage 2: ao[t,h] += sum_s W[t,s] * v'[s,h]
#pragma unroll 8
        for (int s = 0; s < 64; s++) {
            float4 w4 = *(const float4*)&Wt[s][4 * ty];
            float4 v4 = *(const float4*)&vs[s][4 * tx];
            float wr[4] = {w4.x, w4.y, w4.z, w4.w};
            float vr[4] = {v4.x, v4.y, v4.z, v4.w};
#pragma unroll
            for (int i = 0; i < 4; i++)
#pragma unroll
                for (int j = 0; j < 4; j++) ao[i][j] += wr[i] * vr[j];
        }
    }

    // Epilogue: tanh, project with pw, reduce over h
#pragma unroll
    for (int i = 0; i < 4; i++) {
        float part = 0.0f;
#pragma unroll
        for (int j = 0; j < 4; j++) part += tanhf(ao[i][j]) * pw[4 * tx + j];
        red[4 * ty + i][tx] = part;
    }
    __syncthreads();
    if (tid < 64) {
        float ssum = pb[0];
#pragma unroll
        for (int k2 = 0; k2 < 16; k2++) ssum += red[tid][k2];
        out[(size_t)b * T + t0 + tid] = ssum;
    }
}

// ---------------------------------------------------------------------------
extern "C" void kernel_launch(void* const* d_in, const int* in_sizes, int n_in,
                              void* d_out, int out_size) {
    const float* x   = (const float*)d_in[0];
    const float* emb = (const float*)d_in[1];
    const float* kw  = (const float*)d_in[2];
    const float* kb  = (const float*)d_in[3];
    const float* qw  = (const float*)d_in[4];
    const float* qb  = (const float*)d_in[5];
    const float* vw  = (const float*)d_in[6];
    const float* pw  = (const float*)d_in[7];
    const float* pb  = (const float*)d_in[8];
    float* out = (float*)d_out;

    cudaFuncSetAttribute(out_kernel, cudaFuncAttributeMaxDynamicSharedMemorySize, SMEM_E);

    q_kernel<<<(B * T * H) / 256, 256>>>(x, qw, qb);
    kv_kernel<<<(B * S) / 64, 256>>>(emb, kw, kb, vw);
    denom_kernel<<<dim3(S / 64, B), 256>>>();
    scale_v_kernel<<<(B * S * H) / 256, 256>>>();
    out_kernel<<<dim3(T / 64, B), 256, SMEM_E>>>(pw, pb, out);
}

// round 5
// speedup vs baseline: 1.3235x; 1.3235x over previous
#include <cuda_runtime.h>
#include <math.h>
#include <stdint.h>

#define B 4
#define T 4096
#define S 4096
#define E 512
#define H 64
#define RR 16   // Chebyshev order

// 0.125 * log2(e): exp(L) == exp2(L') with this folded into q
#define QSCALE 0.18033688011112042

// ------------------ device scratch ------------------
__device__ float g_c, g_r;                 // x center/radius
__device__ float g_V[RR * 64];             // Chebyshev coeffs per h
__device__ float g_ut[B * RR * T];         // T_m(u_t)  [b][m][t]
__device__ float g_k[B * S * H];           // tanh(emb@kw^T+kb)
__device__ float g_v[B * S * H];           // tanh(emb@vw^T)
__device__ float g_P[B * RR * S];          // V @ k^T    [b][m][s]
__device__ float g_d4[4][B * S];           // denom partials (t-split)
__device__ float g_rd[B * S];              // 1/denom
__device__ float g_acc[4][B * T * H];      // out partials (s-split)

// ------------------ f32x2 helpers ------------------
__device__ __forceinline__ void ffma2(unsigned long long& d, unsigned long long a,
                                      unsigned long long b) {
    asm("fma.rn.f32x2 %0, %1, %2, %0;" : "+l"(d) : "l"(a), "l"(b));
}
__device__ __forceinline__ unsigned long long pk2(float x, float y) {
    unsigned long long r; asm("mov.b64 %0, {%1,%2};" : "=l"(r) : "f"(x), "f"(y)); return r;
}
__device__ __forceinline__ float2 up2(unsigned long long v) {
    float2 r; asm("mov.b64 {%0,%1}, %2;" : "=f"(r.x), "=f"(r.y) : "l"(v)); return r;
}
__device__ __forceinline__ float ex2f(float x) {
    float y; asm("ex2.approx.ftz.f32 %0, %1;" : "=f"(y) : "f"(x)); return y;
}

// ------------------ tiny prep kernels ------------------
__global__ __launch_bounds__(1024) void minmax_kernel(const float* __restrict__ x) {
    __shared__ float smn[1024], smx[1024];
    int tid = threadIdx.x;
    float mn = 1e30f, mx = -1e30f;
    for (int i = tid; i < B * T; i += 1024) {
        float v = x[i]; mn = fminf(mn, v); mx = fmaxf(mx, v);
    }
    smn[tid] = mn; smx[tid] = mx; __syncthreads();
    for (int o = 512; o > 0; o >>= 1) {
        if (tid < o) { smn[tid] = fminf(smn[tid], smn[tid + o]); smx[tid] = fmaxf(smx[tid], smx[tid + o]); }
        __syncthreads();
    }
    if (tid == 0) {
        g_c = 0.5f * (smn[0] + smx[0]);
        g_r = 0.5f * (smx[0] - smn[0]) + 1e-6f;
    }
}

__global__ void coef_kernel(const float* __restrict__ qw, const float* __restrict__ qb) {
    int h = threadIdx.x;  // 64 threads
    double c = (double)g_c, r = (double)g_r;
    double f[RR];
    for (int j = 0; j < RR; j++) {
        double th = 3.14159265358979323846 * (j + 0.5) / RR;
        double xx = c + r * cos(th);
        f[j] = QSCALE * tanh((double)qw[h] * xx + (double)qb[h]);
    }
    for (int m = 0; m < RR; m++) {
        double a = 0.0;
        for (int j = 0; j < RR; j++)
            a += f[j] * cos(3.14159265358979323846 * m * (j + 0.5) / RR);
        a *= (m == 0 ? 1.0 : 2.0) / RR;
        g_V[m * 64 + h] = (float)a;
    }
}

__global__ __launch_bounds__(256) void u_prep(const float* __restrict__ x) {
    int i = blockIdx.x * 256 + threadIdx.x;  // over B*T
    int b = i >> 12, t = i & 4095;
    float u = (x[i] - g_c) / g_r;
    float tm2 = 1.0f, tm1 = u;
    g_ut[(b * RR + 0) * T + t] = 1.0f;
    g_ut[(b * RR + 1) * T + t] = u;
#pragma unroll
    for (int m = 2; m < RR; m++) {
        float tc = 2.0f * u * tm1 - tm2;
        g_ut[(b * RR + m) * T + t] = tc;
        tm2 = tm1; tm1 = tc;
    }
}

// ------------------ kv: [128 rows] x [128 cols = k|v] GEMM over E ------------------
__global__ __launch_bounds__(256) void kv_pk(const float* __restrict__ emb,
                                             const float* __restrict__ kw,
                                             const float* __restrict__ kb,
                                             const float* __restrict__ vw) {
    __shared__ float eT[32][140];
    __shared__ float wT[32][140];
    const int r0 = blockIdx.x * 128;
    const int tid = threadIdx.x;
    const int rg = tid >> 4, cg = tid & 15;  // 16x16, 8x8 microtile

    unsigned long long acc[4][8] = {};  // [row-pair][col]

    for (int e0 = 0; e0 < E; e0 += 32) {
        __syncthreads();
        for (int i = tid; i < 1024; i += 256) {
            int row = i >> 3, ee = (i & 7) * 4;
            float4 v = *(const float4*)(emb + (size_t)(r0 + row) * E + e0 + ee);
            eT[ee][row] = v.x; eT[ee + 1][row] = v.y; eT[ee + 2][row] = v.z; eT[ee + 3][row] = v.w;
        }
        for (int i = tid; i < 1024; i += 256) {
            int col = i >> 3, ee = (i & 7) * 4;
            const float* w = (col < 64) ? (kw + (size_t)col * E) : (vw + (size_t)(col - 64) * E);
            float4 v = *(const float4*)(w + e0 + ee);
            wT[ee][col] = v.x; wT[ee + 1][col] = v.y; wT[ee + 2][col] = v.z; wT[ee + 3][col] = v.w;
        }
        __syncthreads();
#pragma unroll
        for (int e = 0; e < 32; e++) {
            const unsigned long long* ap = (const unsigned long long*)&eT[e][8 * rg];
            unsigned long long a0 = ap[0], a1 = ap[1], a2 = ap[2], a3 = ap[3];
            float4 w0 = *(const float4*)&wT[e][8 * cg];
            float4 w1 = *(const float4*)&wT[e][8 * cg + 4];
            float wv[8] = {w0.x, w0.y, w0.z, w0.w, w1.x, w1.y, w1.z, w1.w};
#pragma unroll
            for (int j = 0; j < 8; j++) {
                unsigned long long bd = pk2(wv[j], wv[j]);
                ffma2(acc[0][j], a0, bd);
                ffma2(acc[1][j], a1, bd);
                ffma2(acc[2][j], a2, bd);
                ffma2(acc[3][j], a3, bd);
            }
        }
    }
#pragma unroll
    for (int i4 = 0; i4 < 4; i4++) {
#pragma unroll
        for (int j = 0; j < 8; j++) {
            float2 v = up2(acc[i4][j]);
            int col = 8 * cg + j;
            size_t row = (size_t)r0 + 8 * rg + 2 * i4;
            if (col < 64) {
                float bias = kb[col];
                g_k[row * H + col] = tanhf(v.x + bias);
                g_k[(row + 1) * H + col] = tanhf(v.y + bias);
            } else {
                g_v[row * H + col - 64] = tanhf(v.x);
                g_v[(row + 1) * H + col - 64] = tanhf(v.y);
            }
        }
    }
}

// ------------------ P[b][m][s] = sum_h V[m][h] * k[b][s][h] ------------------
__global__ __launch_bounds__(128) void p_prep() {
    __shared__ float Vs[RR * 64];
    __shared__ float ks[128][68];
    const int b = blockIdx.y, s0 = blockIdx.x * 128, tid = threadIdx.x;
    for (int i = tid; i < RR * 64; i += 128) Vs[i] = g_V[i];
    for (int i = tid; i < 128 * 16; i += 128) {
        int s = i >> 4, h4 = (i & 15) * 4;
        *(float4*)&ks[s][h4] = *(const float4*)(g_k + ((size_t)(b * S + s0 + s)) * H + h4);
    }
    __syncthreads();
    float kr[64];
#pragma unroll
    for (int h = 0; h < 64; h++) kr[h] = ks[tid][h];
#pragma unroll
    for (int m = 0; m < RR; m++) {
        float a = 0.0f;
#pragma unroll
        for (int h = 0; h < 64; h++) a += Vs[m * 64 + h] * kr[h];
        g_P[(b * RR + m) * S + s0 + tid] = a;
    }
}

// ------------------ denom: d4[ts][b,s] = sum_{t in chunk} exp2(L[t,s]) ------------------
__global__ __launch_bounds__(256) void denom_pk() {
    __shared__ float Ps[RR][136];
    __shared__ float Us[RR][136];
    __shared__ float dsh[128];
    const int b = blockIdx.z, ts = blockIdx.y, s0 = blockIdx.x * 128;
    const int tid = threadIdx.x;
    const int tg = tid >> 4, sg = tid & 15;  // 16x16: 8t x 8s microtile

    for (int i = tid; i < RR * 128; i += 256) {
        int m = i >> 7, s = i & 127;
        Ps[m][s] = g_P[(b * RR + m) * S + s0 + s];
    }
    if (tid < 128) dsh[tid] = 0.0f;

    float dsum[8] = {};
    for (int tt = 0; tt < 8; tt++) {
        const int t0 = ts * 1024 + tt * 128;
        __syncthreads();
        for (int i = tid; i < RR * 128; i += 256) {
            int m = i >> 7, t = i & 127;
            Us[m][t] = g_ut[(b * RR + m) * T + t0 + t];
        }
        __syncthreads();

        unsigned long long acc[4][8] = {};
#pragma unroll
        for (int m = 0; m < RR; m++) {
            const unsigned long long* ap = (const unsigned long long*)&Us[m][8 * tg];
            unsigned long long a0 = ap[0], a1 = ap[1], a2 = ap[2], a3 = ap[3];
            float4 p0 = *(const float4*)&Ps[m][8 * sg];
            float4 p1 = *(const float4*)&Ps[m][8 * sg + 4];
            float pv[8] = {p0.x, p0.y, p0.z, p0.w, p1.x, p1.y, p1.z, p1.w};
#pragma unroll
            for (int j = 0; j < 8; j++) {
                unsigned long long bd = pk2(pv[j], pv[j]);
                ffma2(acc[0][j], a0, bd);
                ffma2(acc[1][j], a1, bd);
                ffma2(acc[2][j], a2, bd);
                ffma2(acc[3][j], a3, bd);
            }
        }
#pragma unroll
        for (int i4 = 0; i4 < 4; i4++)
#pragma unroll
            for (int j = 0; j < 8; j++) {
                float2 v = up2(acc[i4][j]);
                dsum[j] += ex2f(v.x) + ex2f(v.y);
            }
    }
    __syncthreads();
#pragma unroll
    for (int j = 0; j < 8; j++) atomicAdd(&dsh[8 * sg + j], dsum[j]);
    __syncthreads();
    if (tid < 128) g_d4[ts][b * S + s0 + tid] = dsh[tid];
}

__global__ __launch_bounds__(256) void rd_prep() {
    int i = blockIdx.x * 256 + threadIdx.x;
    g_rd[i] = 1.0f / (g_d4[0][i] + g_d4[1][i] + g_d4[2][i] + g_d4[3][i]);
}

// ------------------ out pass: acc[ss][b,t,h] = sum_{s in chunk} W'[t,s] v[s,h] ------------------
// smem floats: Us 16*136 | Ps 16*72 | W 128*69 | vs 64*68 | rds 64
#define OUS 0
#define OPS 2176
#define OWS 3328
#define OVS 12160
#define ORD 16512
#define OSMEM ((16512 + 64) * 4)

__global__ __launch_bounds__(128, 3) void out_pk() {
    extern __shared__ __align__(16) float sm[];
    const int b = blockIdx.z, ss = blockIdx.y, tb0 = blockIdx.x * 128;
    const int tid = threadIdx.x;
    const int tg = tid >> 3, xg = tid & 7;  // 16 x 8 : 8t x 8(s|h) microtile

    for (int i = tid; i < RR * 128; i += 128) {
        int m = i >> 7, t = i & 127;
        sm[OUS + m * 136 + t] = g_ut[(b * RR + m) * T + tb0 + t];
    }

    unsigned long long oacc[8][4] = {};  // [t][h-pair]

    for (int st = 0; st < 16; st++) {
        const int s0 = ss * 1024 + st * 64;
        __syncthreads();
        for (int i = tid; i < RR * 64; i += 128) {
            int m = i >> 6, s = i & 63;
            sm[OPS + m * 72 + s] = g_P[(b * RR + m) * S + s0 + s];
        }
        for (int i = tid; i < 64 * 16; i += 128) {
            int s = i >> 4, h4 = (i & 15) * 4;
            *(float4*)&sm[OVS + s * 68 + h4] =
                *(const float4*)(g_v + ((size_t)(b * S + s0 + s)) * H + h4);
        }
        if (tid < 64) sm[ORD + tid] = g_rd[b * S + s0 + tid];
        __syncthreads();

        // stage 1: L[8t x 8s] = sum_m U*P ; W = exp2(L)*rd
        unsigned long long lac[4][8] = {};
#pragma unroll
        for (int m = 0; m < RR; m++) {
            const unsigned long long* ap = (const unsigned long long*)&sm[OUS + m * 136 + 8 * tg];
            unsigned long long a0 = ap[0], a1 = ap[1], a2 = ap[2], a3 = ap[3];
            float4 p0 = *(const float4*)&sm[OPS + m * 72 + 8 * xg];
            float4 p1 = *(const float4*)&sm[OPS + m * 72 + 8 * xg + 4];
            float pv[8] = {p0.x, p0.y, p0.z, p0.w, p1.x, p1.y, p1.z, p1.w};
#pragma unroll
            for (int j = 0; j < 8; j++) {
                unsigned long long bd = pk2(pv[j], pv[j]);
                ffma2(lac[0][j], a0, bd);
                ffma2(lac[1][j], a1, bd);
                ffma2(lac[2][j], a2, bd);
                ffma2(lac[3][j], a3, bd);
            }
        }
#pragma unroll
        for (int i4 = 0; i4 < 4; i4++)
#pragma unroll
            for (int j = 0; j < 8; j++) {
                float2 v = up2(lac[i4][j]);
                float rs = sm[ORD + 8 * xg + j];
                sm[OWS + (8 * tg + 2 * i4) * 69 + 8 * xg + j] = ex2f(v.x) * rs;
                sm[OWS + (8 * tg + 2 * i4 + 1) * 69 + 8 * xg + j] = ex2f(v.y) * rs;
            }
        __syncthreads();

        // stage 2: oacc[8t x 8h] += W[t][s] * v[s][h], pack over h pairs
#pragma unroll 4
        for (int s = 0; s < 64; s++) {
            const unsigned long long* vp = (const unsigned long long*)&sm[OVS + s * 68 + 8 * xg];
            unsigned long long v0 = vp[0], v1 = vp[1], v2 = vp[2], v3 = vp[3];
#pragma unroll
            for (int i = 0; i < 8; i++) {
                float wv = sm[OWS + (8 * tg + i) * 69 + s];
                unsigned long long wd = pk2(wv, wv);
                ffma2(oacc[i][0], wd, v0);
                ffma2(oacc[i][1], wd, v1);
                ffma2(oacc[i][2], wd, v2);
                ffma2(oacc[i][3], wd, v3);
            }
        }
    }

#pragma unroll
    for (int i = 0; i < 8; i++)
#pragma unroll
        for (int j4 = 0; j4 < 4; j4++) {
            float2 o = up2(oacc[i][j4]);
            size_t base = ((size_t)(b * T) + tb0 + 8 * tg + i) * H + 8 * xg + 2 * j4;
            *(float2*)&g_acc[ss][base] = o;
        }
}

// ------------------ final: out[b,t] = pb + sum_h pw[h]*tanh(sum_ss acc) ------------------
__global__ __launch_bounds__(256) void final_ep(const float* __restrict__ pw,
                                                const float* __restrict__ pb,
                                                float* __restrict__ out) {
    __shared__ float red[64][5];
    __shared__ float pws[64];
    const int tid = threadIdx.x;
    if (tid < 64) pws[tid] = pw[tid];
    __syncthreads();
    const size_t bt0 = (size_t)blockIdx.x * 64;
    const int tl = tid >> 2, hq = tid & 3;
    const size_t base = (bt0 + tl) * H + hq * 16;
    float p = 0.0f;
#pragma unroll
    for (int h = 0; h < 16; h += 4) {
        float4 a0 = *(const float4*)&g_acc[0][base + h];
        float4 a1 = *(const float4*)&g_acc[1][base + h];
        float4 a2 = *(const float4*)&g_acc[2][base + h];
        float4 a3 = *(const float4*)&g_acc[3][base + h];
        p += tanhf(a0.x + a1.x + a2.x + a3.x) * pws[hq * 16 + h];
        p += tanhf(a0.y + a1.y + a2.y + a3.y) * pws[hq * 16 + h + 1];
        p += tanhf(a0.z + a1.z + a2.z + a3.z) * pws[hq * 16 + h + 2];
        p += tanhf(a0.w + a1.w + a2.w + a3.w) * pws[hq * 16 + h + 3];
    }
    red[tl][hq] = p;
    __syncthreads();
    if (hq == 0)
        out[bt0 + tl] = pb[0] + red[tl][0] + red[tl][1] + red[tl][2] + red[tl][3];
}

// ---------------------------------------------------------------------------
extern "C" void kernel_launch(void* const* d_in, const int* in_sizes, int n_in,
                              void* d_out, int out_size) {
    const float* x   = (const float*)d_in[0];
    const float* emb = (const float*)d_in[1];
    const float* kw  = (const float*)d_in[2];
    const float* kb  = (const float*)d_in[3];
    const float* qw  = (const float*)d_in[4];
    const float* qb  = (const float*)d_in[5];
    const float* vw  = (const float*)d_in[6];
    const float* pw  = (const float*)d_in[7];
    const float* pb  = (const float*)d_in[8];
    float* out = (float*)d_out;

    cudaFuncSetAttribute(out_pk, cudaFuncAttributeMaxDynamicSharedMemorySize, OSMEM);

    minmax_kernel<<<1, 1024>>>(x);
    coef_kernel<<<1, 64>>>(qw, qb);
    u_prep<<<(B * T) / 256, 256>>>(x);
    kv_pk<<<(B * S) / 128, 256>>>(emb, kw, kb, vw);
    p_prep<<<dim3(S / 128, B), 128>>>();
    denom_pk<<<dim3(S / 128, 4, B), 256>>>();
    rd_prep<<<(B * S) / 256, 256>>>();
    out_pk<<<dim3(T / 128, 4, B), 128, OSMEM>>>();
    final_ep<<<(B * T) / 64, 256>>>(pw, pb, out);
}

// round 6
// speedup vs baseline: 1.3577x; 1.0259x over previous
#include <cuda_runtime.h>
#include <math.h>
#include <stdint.h>

#define B 4
#define T 4096
#define S 4096
#define E 512
#define H 64
#define RR 16

#define QSCALE 0.18033688011112042

typedef unsigned long long u64;

// ------------------ device scratch ------------------
__device__ float g_c, g_r;
__device__ float g_V[RR * 64];
__device__ float g_ut[B * RR * T];
__device__ float g_k[B * S * H];
__device__ float g_v[B * S * H];
__device__ float g_P[B * RR * S];
__device__ float g_d4[4][B * S];
__device__ float g_rd[B * S];
__device__ float g_acc[8][B * T * H];

// ------------------ helpers ------------------
__device__ __forceinline__ void ffma2(u64& d, u64 a, u64 b) {
    asm("fma.rn.f32x2 %0, %1, %2, %0;" : "+l"(d) : "l"(a), "l"(b));
}
__device__ __forceinline__ u64 pk2(float x, float y) {
    u64 r; asm("mov.b64 %0, {%1,%2};" : "=l"(r) : "f"(x), "f"(y)); return r;
}
__device__ __forceinline__ float2 up2(u64 v) {
    float2 r; asm("mov.b64 {%0,%1}, %2;" : "=f"(r.x), "=f"(r.y) : "l"(v)); return r;
}
__device__ __forceinline__ float ex2f(float x) {
    float y; asm("ex2.approx.ftz.f32 %0, %1;" : "=f"(y) : "f"(x)); return y;
}

// ------------------ tiny prep ------------------
__global__ __launch_bounds__(1024) void minmax_kernel(const float* __restrict__ x) {
    __shared__ float smn[1024], smx[1024];
    int tid = threadIdx.x;
    float mn = 1e30f, mx = -1e30f;
    for (int i = tid; i < B * T; i += 1024) {
        float v = x[i]; mn = fminf(mn, v); mx = fmaxf(mx, v);
    }
    smn[tid] = mn; smx[tid] = mx; __syncthreads();
    for (int o = 512; o > 0; o >>= 1) {
        if (tid < o) { smn[tid] = fminf(smn[tid], smn[tid+o]); smx[tid] = fmaxf(smx[tid], smx[tid+o]); }
        __syncthreads();
    }
    if (tid == 0) { g_c = 0.5f*(smn[0]+smx[0]); g_r = 0.5f*(smx[0]-smn[0]) + 1e-6f; }
}

__global__ void coef_kernel(const float* __restrict__ qw, const float* __restrict__ qb) {
    int h = threadIdx.x;
    double c = (double)g_c, r = (double)g_r;
    double f[RR];
    for (int j = 0; j < RR; j++) {
        double th = 3.14159265358979323846 * (j + 0.5) / RR;
        f[j] = QSCALE * tanh((double)qw[h] * (c + r*cos(th)) + (double)qb[h]);
    }
    for (int m = 0; m < RR; m++) {
        double a = 0.0;
        for (int j = 0; j < RR; j++) a += f[j] * cos(3.14159265358979323846 * m * (j+0.5) / RR);
        a *= (m == 0 ? 1.0 : 2.0) / RR;
        g_V[m * 64 + h] = (float)a;
    }
}

__global__ __launch_bounds__(256) void u_prep(const float* __restrict__ x) {
    int i = blockIdx.x * 256 + threadIdx.x;
    int b = i >> 12, t = i & 4095;
    float u = (x[i] - g_c) / g_r;
    float tm2 = 1.0f, tm1 = u;
    g_ut[(b*RR+0)*T + t] = 1.0f;
    g_ut[(b*RR+1)*T + t] = u;
#pragma unroll
    for (int m = 2; m < RR; m++) {
        float tc = 2.0f*u*tm1 - tm2;
        g_ut[(b*RR+m)*T + t] = tc;
        tm2 = tm1; tm1 = tc;
    }
}

// ------------------ kv: 64 rows x 128 cols, e-parity packed ------------------
__global__ __launch_bounds__(256, 2) void kv_pk(const float* __restrict__ emb,
                                                const float* __restrict__ kw,
                                                const float* __restrict__ kb,
                                                const float* __restrict__ vw) {
    __shared__ __align__(16) float2 ei[16 * 66];    // [ep][row]
    __shared__ __align__(16) float2 wi[16 * 130];   // [ep][col]
    const int r0 = blockIdx.x * 64;
    const int tid = threadIdx.x;
    const int rg = tid >> 5, cg = tid & 31;   // 8 row-groups x 32 col-groups

    u64 acc[8][4] = {};

    for (int e0 = 0; e0 < E; e0 += 32) {
        __syncthreads();
        for (int i = tid; i < 512; i += 256) {
            int r = i >> 3, e4 = (i & 7) * 4;
            float4 v = *(const float4*)(emb + (size_t)(r0 + r) * E + e0 + e4);
            ei[((e4 >> 1) + 0) * 66 + r] = make_float2(v.x, v.y);
            ei[((e4 >> 1) + 1) * 66 + r] = make_float2(v.z, v.w);
        }
        for (int i = tid; i < 1024; i += 256) {
            int c = i >> 3, e4 = (i & 7) * 4;
            const float* w = (c < 64) ? (kw + (size_t)c * E) : (vw + (size_t)(c - 64) * E);
            float4 v = *(const float4*)(w + e0 + e4);
            wi[((e4 >> 1) + 0) * 130 + c] = make_float2(v.x, v.y);
            wi[((e4 >> 1) + 1) * 130 + c] = make_float2(v.z, v.w);
        }
        __syncthreads();
#pragma unroll
        for (int ep = 0; ep < 16; ep++) {
            const u64* ap = (const u64*)&ei[ep * 66 + 8 * rg];
            ulonglong2 a01 = *(const ulonglong2*)(ap + 0);
            ulonglong2 a23 = *(const ulonglong2*)(ap + 2);
            ulonglong2 a45 = *(const ulonglong2*)(ap + 4);
            ulonglong2 a67 = *(const ulonglong2*)(ap + 6);
            u64 ar[8] = {a01.x, a01.y, a23.x, a23.y, a45.x, a45.y, a67.x, a67.y};
            const u64* bp = (const u64*)&wi[ep * 130 + 4 * cg];
            ulonglong2 b01 = *(const ulonglong2*)(bp + 0);
            ulonglong2 b23 = *(const ulonglong2*)(bp + 2);
            u64 br[4] = {b01.x, b01.y, b23.x, b23.y};
#pragma unroll
            for (int j = 0; j < 8; j++)
#pragma unroll
                for (int c = 0; c < 4; c++) ffma2(acc[j][c], ar[j], br[c]);
        }
    }
#pragma unroll
    for (int j = 0; j < 8; j++) {
        size_t row = (size_t)r0 + 8 * rg + j;
#pragma unroll
        for (int c = 0; c < 4; c++) {
            float2 v = up2(acc[j][c]);
            float val = v.x + v.y;
            int col = 4 * cg + c;
            if (col < 64) g_k[row * H + col] = tanhf(val + kb[col]);
            else          g_v[row * H + col - 64] = tanhf(val);
        }
    }
}

// ------------------ P[b][m][s] = sum_h V[m][h] k[b][s][h] ------------------
__global__ __launch_bounds__(128) void p_prep() {
    __shared__ float Vs[RR * 64];
    __shared__ float ks[128][68];
    const int b = blockIdx.y, s0 = blockIdx.x * 128, tid = threadIdx.x;
    for (int i = tid; i < RR * 64; i += 128) Vs[i] = g_V[i];
    for (int i = tid; i < 128 * 16; i += 128) {
        int s = i >> 4, h4 = (i & 15) * 4;
        *(float4*)&ks[s][h4] = *(const float4*)(g_k + ((size_t)(b*S + s0 + s)) * H + h4);
    }
    __syncthreads();
    float kr[64];
#pragma unroll
    for (int h = 0; h < 64; h++) kr[h] = ks[tid][h];
#pragma unroll
    for (int m = 0; m < RR; m++) {
        float a = 0.0f;
#pragma unroll
        for (int h = 0; h < 64; h++) a += Vs[m * 64 + h] * kr[h];
        g_P[(b*RR + m) * S + s0 + tid] = a;
    }
}

// ------------------ denom: t-pair packed, dup-P operand ------------------
// Psd layout per m: 16 blocks (of 8 s) x 20 words; Us [m][132]
__global__ __launch_bounds__(256, 2) void denom_pk() {
    __shared__ __align__(16) float Psd[16 * 320];
    __shared__ __align__(16) float Us[16 * 132];
    __shared__ float dsh[128];
    const int b = blockIdx.z, ts = blockIdx.y, s0 = blockIdx.x * 128;
    const int tid = threadIdx.x;
    const int tg = tid >> 4, sg = tid & 15;

    for (int i = tid; i < 2048; i += 256) {
        int m = i >> 7, s = i & 127;
        float p = g_P[(b*RR + m) * S + s0 + s];
        *(float2*)&Psd[m * 320 + (s >> 3) * 20 + (s & 7) * 2] = make_float2(p, p);
    }
    if (tid < 128) dsh[tid] = 0.0f;

    float dsum[8] = {};
    for (int tt = 0; tt < 8; tt++) {
        const int t0 = ts * 1024 + tt * 128;
        __syncthreads();
        for (int i = tid; i < 2048; i += 256) {
            int m = i >> 7, t = i & 127;
            Us[m * 132 + t] = g_ut[(b*RR + m) * T + t0 + t];
        }
        __syncthreads();

        u64 lac[4][8] = {};
#pragma unroll
        for (int m = 0; m < RR; m++) {
            const float* ur = &Us[m * 132 + 8 * tg];
            u64 a0 = *(const u64*)(ur + 0);
            u64 a1 = *(const u64*)(ur + 2);
            u64 a2 = *(const u64*)(ur + 4);
            u64 a3 = *(const u64*)(ur + 6);
            const u64* bp = (const u64*)&Psd[m * 320 + sg * 20];
            ulonglong2 b01 = *(const ulonglong2*)(bp + 0);
            ulonglong2 b23 = *(const ulonglong2*)(bp + 2);
            ulonglong2 b45 = *(const ulonglong2*)(bp + 4);
            ulonglong2 b67 = *(const ulonglong2*)(bp + 6);
            u64 br[8] = {b01.x, b01.y, b23.x, b23.y, b45.x, b45.y, b67.x, b67.y};
#pragma unroll
            for (int j = 0; j < 8; j++) {
                ffma2(lac[0][j], a0, br[j]);
                ffma2(lac[1][j], a1, br[j]);
                ffma2(lac[2][j], a2, br[j]);
                ffma2(lac[3][j], a3, br[j]);
            }
        }
#pragma unroll
        for (int i4 = 0; i4 < 4; i4++)
#pragma unroll
            for (int j = 0; j < 8; j++) {
                float2 v = up2(lac[i4][j]);
                dsum[j] += ex2f(v.x) + ex2f(v.y);
            }
    }
    __syncthreads();
#pragma unroll
    for (int j = 0; j < 8; j++) atomicAdd(&dsh[8 * sg + j], dsum[j]);
    __syncthreads();
    if (tid < 128) g_d4[ts][b*S + s0 + tid] = dsh[tid];
}

__global__ __launch_bounds__(256) void rd_prep() {
    int i = blockIdx.x * 256 + threadIdx.x;
    g_rd[i] = 1.0f / (g_d4[0][i] + g_d4[1][i] + g_d4[2][i] + g_d4[3][i]);
}

// ------------------ out pass ------------------
// smem (floats): Us [16][132] | Psd 16 x 160 | Wsm 128x66 + tg pads | vi 32 x 160 | rds 64
#define OUS 0
#define OPS 2112
#define OWS (2112 + 2560)
#define OVI (OWS + 8512)
#define ORD (OVI + 5120)
#define OSMEM ((ORD + 64) * 4)

__global__ __launch_bounds__(128, 2) void out_pk() {
    extern __shared__ __align__(16) float sm[];
    const int b = blockIdx.z, ss = blockIdx.y, tb0 = blockIdx.x * 128;
    const int tid = threadIdx.x;
    const int tg = tid >> 3, xg = tid & 7;   // 16 t-groups x 8 (s|h)-groups

    for (int i = tid; i < 2048; i += 128) {
        int m = i >> 7, t = i & 127;
        sm[OUS + m * 132 + t] = g_ut[(b*RR + m) * T + tb0 + t];
    }

    u64 oacc[8][8] = {};   // [t-row][h], halves = even/odd s partial sums

    for (int st = 0; st < 8; st++) {
        const int s0 = ss * 512 + st * 64;
        __syncthreads();
        // Psd: dup pairs, block-20 layout (8 s per block)
        for (int i = tid; i < 1024; i += 128) {
            int m = i >> 6, s = i & 63;
            float p = g_P[(b*RR + m) * S + s0 + s];
            *(float2*)&sm[OPS + m * 160 + (s >> 3) * 20 + (s & 7) * 2] = make_float2(p, p);
        }
        // vi: s-parity interleaved v pairs, block-20 layout over h
        for (int i = tid; i < 4096; i += 128) {
            int s = i >> 6, h = i & 63;
            float v = g_v[((size_t)(b*S + s0 + s)) * H + h];
            sm[OVI + (s >> 1) * 160 + (h >> 3) * 20 + (h & 7) * 2 + (s & 1)] = v;
        }
        if (tid < 64) sm[ORD + tid] = g_rd[b*S + s0 + tid];
        __syncthreads();

        // ---- stage 1: L[8t x 8s] over m, t-pair packed ----
        u64 lac[4][8] = {};
#pragma unroll
        for (int m = 0; m < RR; m++) {
            const float* ur = &sm[OUS + m * 132 + 8 * tg];
            u64 a0 = *(const u64*)(ur + 0);
            u64 a1 = *(const u64*)(ur + 2);
            u64 a2 = *(const u64*)(ur + 4);
            u64 a3 = *(const u64*)(ur + 6);
            const u64* bp = (const u64*)&sm[OPS + m * 160 + xg * 20];
            ulonglong2 b01 = *(const ulonglong2*)(bp + 0);
            ulonglong2 b23 = *(const ulonglong2*)(bp + 2);
            ulonglong2 b45 = *(const ulonglong2*)(bp + 4);
            ulonglong2 b67 = *(const ulonglong2*)(bp + 6);
            u64 br[8] = {b01.x, b01.y, b23.x, b23.y, b45.x, b45.y, b67.x, b67.y};
#pragma unroll
            for (int j = 0; j < 8; j++) {
                ffma2(lac[0][j], a0, br[j]);
                ffma2(lac[1][j], a1, br[j]);
                ffma2(lac[2][j], a2, br[j]);
                ffma2(lac[3][j], a3, br[j]);
            }
        }
        // W = exp2(L)*rd -> Wsm row-major (stride 66 + 4-word pad per 8 rows)
#pragma unroll
        for (int i4 = 0; i4 < 4; i4++) {
            int t0 = 8 * tg + 2 * i4;
            int ro = t0 * 66 + tg * 4;
#pragma unroll
            for (int j = 0; j < 8; j++) {
                float2 v = up2(lac[i4][j]);
                float rs = sm[ORD + 8 * xg + j];
                sm[OWS + ro + 8 * xg + j] = ex2f(v.x) * rs;
                sm[OWS + ro + 66 + 8 * xg + j] = ex2f(v.y) * rs;
            }
        }
        __syncthreads();

        // ---- stage 2: oacc[8t x 8h] += W[t][s-pair] * v[s-pair][h] ----
#pragma unroll 2
        for (int sp = 0; sp < 32; sp++) {
            const u64* vp = (const u64*)&sm[OVI + sp * 160 + xg * 20];
            ulonglong2 v01 = *(const ulonglong2*)(vp + 0);
            ulonglong2 v23 = *(const ulonglong2*)(vp + 2);
            ulonglong2 v45 = *(const ulonglong2*)(vp + 4);
            ulonglong2 v67 = *(const ulonglong2*)(vp + 6);
            u64 bb[8] = {v01.x, v01.y, v23.x, v23.y, v45.x, v45.y, v67.x, v67.y};
            const float* wr = &sm[OWS + 8 * tg * 66 + tg * 4 + 2 * sp];
#pragma unroll
            for (int i = 0; i < 8; i++) {
                u64 a = *(const u64*)(wr + i * 66);
                ffma2(oacc[i][0], a, bb[0]);
                ffma2(oacc[i][1], a, bb[1]);
                ffma2(oacc[i][2], a, bb[2]);
                ffma2(oacc[i][3], a, bb[3]);
                ffma2(oacc[i][4], a, bb[4]);
                ffma2(oacc[i][5], a, bb[5]);
                ffma2(oacc[i][6], a, bb[6]);
                ffma2(oacc[i][7], a, bb[7]);
            }
        }
    }

#pragma unroll
    for (int i = 0; i < 8; i++) {
        size_t base = ((size_t)(b*T) + tb0 + 8 * tg + i) * H + 8 * xg;
#pragma unroll
        for (int h = 0; h < 8; h += 2) {
            float2 va = up2(oacc[i][h]);
            float2 vb = up2(oacc[i][h + 1]);
            *(float2*)&g_acc[ss][base + h] = make_float2(va.x + va.y, vb.x + vb.y);
        }
    }
}

// ------------------ final epilogue ------------------
__global__ __launch_bounds__(256) void final_ep(const float* __restrict__ pw,
                                                const float* __restrict__ pb,
                                                float* __restrict__ out) {
    __shared__ float red[64][5];
    __shared__ float pws[64];
    const int tid = threadIdx.x;
    if (tid < 64) pws[tid] = pw[tid];
    __syncthreads();
    const size_t bt0 = (size_t)blockIdx.x * 64;
    const int tl = tid >> 2, hq = tid & 3;
    const size_t base = (bt0 + tl) * H + hq * 16;
    float p = 0.0f;
#pragma unroll
    for (int h = 0; h < 16; h += 4) {
        float4 sum = make_float4(0.f, 0.f, 0.f, 0.f);
#pragma unroll
        for (int ss = 0; ss < 8; ss++) {
            float4 a = *(const float4*)&g_acc[ss][base + h];
            sum.x += a.x; sum.y += a.y; sum.z += a.z; sum.w += a.w;
        }
        p += tanhf(sum.x) * pws[hq * 16 + h];
        p += tanhf(sum.y) * pws[hq * 16 + h + 1];
        p += tanhf(sum.z) * pws[hq * 16 + h + 2];
        p += tanhf(sum.w) * pws[hq * 16 + h + 3];
    }
    red[tl][hq] = p;
    __syncthreads();
    if (hq == 0)
        out[bt0 + tl] = pb[0] + red[tl][0] + red[tl][1] + red[tl][2] + red[tl][3];
}

// ---------------------------------------------------------------------------
extern "C" void kernel_launch(void* const* d_in, const int* in_sizes, int n_in,
                              void* d_out, int out_size) {
    const float* x   = (const float*)d_in[0];
    const float* emb = (const float*)d_in[1];
    const float* kw  = (const float*)d_in[2];
    const float* kb  = (const float*)d_in[3];
    const float* qw  = (const float*)d_in[4];
    const float* qb  = (const float*)d_in[5];
    const float* vw  = (const float*)d_in[6];
    const float* pw  = (const float*)d_in[7];
    const float* pb  = (const float*)d_in[8];
    float* out = (float*)d_out;

    cudaFuncSetAttribute(out_pk, cudaFuncAttributeMaxDynamicSharedMemorySize, OSMEM);

    minmax_kernel<<<1, 1024>>>(x);
    coef_kernel<<<1, 64>>>(qw, qb);
    u_prep<<<(B * T) / 256, 256>>>(x);
    kv_pk<<<(B * S) / 64, 256>>>(emb, kw, kb, vw);
    p_prep<<<dim3(S / 128, B), 128>>>();
    denom_pk<<<dim3(S / 128, 4, B), 256>>>();
    rd_prep<<<(B * S) / 256, 256>>>();
    out_pk<<<dim3(T / 128, 8, B), 128, OSMEM>>>();
    final_ep<<<(B * T) / 64, 256>>>(pw, pb, out);
}